// round 12
// baseline (speedup 1.0000x reference)
#include <cuda_runtime.h>
#include <cuda_bf16.h>
#include <cstdint>
typedef uint32_t u32;

// ---- smem byte map: A_hi[0,64K) A_lo[64K,128K) Wbuf[131072,+2x40960) bias, div ----
#define ALO    65536u
#define WOFF   131072u
#define BIOFF  212992u
#define DIVOFF 215296u
#define SMEMSZ 219392u

// 18 ldmatrix-ready weight chunk images: L0 2x40960, L1 8x40960, L2 8x10240
static __device__ __align__(16) unsigned char gImg[491520];
static __device__ float gBias[576];

__global__ void prep_kernel(const float* __restrict__ t,
                            const float* __restrict__ W0, const float* __restrict__ b0,
                            const float* __restrict__ W1, const float* __restrict__ b1,
                            const float* __restrict__ W2, const float* __restrict__ b2)
{
    int n = blockIdx.x, x = threadIdx.x;         // n: out-neuron, x: k
    {   // W1 [256][257]: chunks of 32 k, rows padded to 80B, hi then lo plane
        float v = W1[n * 257 + x + 1];
        __nv_bfloat16 h = __float2bfloat16(v);
        __nv_bfloat16 l = __float2bfloat16(v - __bfloat162float(h));
        u32 off = 81920u + (u32)(x >> 5) * 40960u + n * 80u + (x & 31) * 2u;
        *(__nv_bfloat16*)(gImg + off) = h;
        *(__nv_bfloat16*)(gImg + off + 20480u) = l;
    }
    if (x < 64) {   // W0 [256][65], K=64 -> 2 chunks
        float v = W0[n * 65 + x + 1];
        __nv_bfloat16 h = __float2bfloat16(v);
        __nv_bfloat16 l = __float2bfloat16(v - __bfloat162float(h));
        u32 off = (u32)(x >> 5) * 40960u + n * 80u + (x & 31) * 2u;
        *(__nv_bfloat16*)(gImg + off) = h;
        *(__nv_bfloat16*)(gImg + off + 20480u) = l;
    }
    if (n < 64) {   // W2 [64][257], 64 rows -> 8 chunks of 10240
        float v = W2[n * 257 + x + 1];
        __nv_bfloat16 h = __float2bfloat16(v);
        __nv_bfloat16 l = __float2bfloat16(v - __bfloat162float(h));
        u32 off = 409600u + (u32)(x >> 5) * 10240u + n * 80u + (x & 31) * 2u;
        *(__nv_bfloat16*)(gImg + off) = h;
        *(__nv_bfloat16*)(gImg + off + 5120u) = l;
    }
    if (n == 0) {
        float tv = t[0];
        gBias[x] = b0[x] + tv * W0[x * 65];
        gBias[256 + x] = b1[x] + tv * W1[x * 257];
        if (x < 64) gBias[512 + x] = b2[x] + tv * W2[x * 257];
    }
}

// ---------------- helpers ----------------
__device__ __forceinline__ u32 s2u(const void* p) {
    u32 a; asm("{.reg .u64 t; cvta.to.shared.u64 t,%1; cvt.u32.u64 %0,t;}" : "=r"(a) : "l"(p)); return a;
}
__device__ __forceinline__ void cp16(u32 s, const void* g) {
    asm volatile("cp.async.cg.shared.global [%0],[%1],16;" :: "r"(s), "l"(g));
}
__device__ __forceinline__ void ldsm4(u32* r, u32 a) {
    asm volatile("ldmatrix.sync.aligned.m8n8.x4.shared.b16 {%0,%1,%2,%3},[%4];"
        : "=r"(r[0]), "=r"(r[1]), "=r"(r[2]), "=r"(r[3]) : "r"(a));
}
__device__ __forceinline__ void mma16816(float* c, const u32* a, const u32* b) {
    asm volatile("mma.sync.aligned.m16n8k16.row.col.f32.bf16.bf16.f32 "
        "{%0,%1,%2,%3},{%4,%5,%6,%7},{%8,%9},{%0,%1,%2,%3};"
        : "+f"(c[0]), "+f"(c[1]), "+f"(c[2]), "+f"(c[3])
        : "r"(a[0]), "r"(a[1]), "r"(a[2]), "r"(a[3]), "r"(b[0]), "r"(b[1]));
}
__device__ __forceinline__ void actf(float z, float& s, float& h) {
    float ea  = __expf(-fabsf(z));
    float inv = __fdividef(1.f, 1.f + ea);
    s = (z >= 0.f) ? inv : ea * inv;
    h = fmaxf(z, 0.f) + __logf(1.f + ea);
}
__device__ __forceinline__ const unsigned char* chunk_src(int i, u32& sz) {
    if (i < 2)  { sz = 40960; return gImg + i * 40960; }
    if (i < 10) { sz = 40960; return gImg + 81920 + (i - 2) * 40960; }
    sz = 10240; return gImg + 409600 + (i - 10) * 10240;
}
// swizzled byte offset into activation plane: row stride 512B, 16B granule XOR
__device__ __forceinline__ u32 aoff(int row, int kb) {
    return (u32)row * 512u + ((((u32)kb >> 4) ^ (row & 7)) << 4) + (kb & 15);
}

// 3-term split accumulate: AhWh + AlWh + AhWl  (b[0..1]=Wh frag, b[2..3]=Wl frag)
#define MMA3(acc_, af_, b_) do { \
    mma16816(acc_, af_[0], b_); \
    mma16816(acc_, af_[1], b_); \
    mma16816(acc_, af_[0], (b_) + 2); \
} while (0)

__global__ void __launch_bounds__(512, 1)
odefunc_kernel(const float* __restrict__ y, const float* __restrict__ e,
               float* __restrict__ out)
{
    extern __shared__ char sm[];
    const u32 sb = s2u(sm);
    const int tid = threadIdx.x, lane = tid & 31, w = tid >> 5;
    const int mg = w >> 2, ng = w & 3;          // 4 x 4 warp grid
    const size_t r0 = (size_t)blockIdx.x * 64;

    // ---- stage inputs: row 2b = y_state, row 2b+1 = e; bf16 hi/lo planes ----
    for (int p = tid; p < 4096; p += 512) {
        int m = p >> 5, kp = p & 31, b = m >> 1;
        float v0, v1;
        if (m & 1) { v0 = e[(r0 + b) * 64 + 2 * kp]; v1 = e[(r0 + b) * 64 + 2 * kp + 1]; }
        else       { v0 = y[(r0 + b) * 65 + 2 * kp]; v1 = y[(r0 + b) * 65 + 2 * kp + 1]; }
        __nv_bfloat162 hp, lp;
        hp.x = __float2bfloat16(v0); hp.y = __float2bfloat16(v1);
        lp.x = __float2bfloat16(v0 - __bfloat162float(hp.x));
        lp.y = __float2bfloat16(v1 - __bfloat162float(hp.y));
        u32 o = aoff(m, kp * 4);
        *(__nv_bfloat162*)(sm + o) = hp;
        *(__nv_bfloat162*)(sm + ALO + o) = lp;
    }
    for (int i = tid; i < 576; i += 512) ((float*)(sm + BIOFF))[i] = gBias[i];

    // prime chunk 0
    { u32 sz; const unsigned char* s = chunk_src(0, sz);
      for (u32 r = tid * 16; r < sz; r += 8192) cp16(sb + WOFF + r, s + r);
      asm volatile("cp.async.commit_group;"); }

    float acc[2][8][4];
    const float* bias = (const float*)(sm + BIOFF);
    const int g = lane >> 2, c2 = (lane & 3) * 2;
    const bool ev = !(g & 1);

    // B ldsm.x4 lane-address components (hi plane lanes 0-15, lo plane lanes 16-31)
    const u32 brow80 = (u32)(lane & 7) * 80u;
    const u32 bksel  = ((lane >> 3) & 1) ? 16u : 0u;
    const u32 bplane = (u32)((lane >> 4) & 1);      // 1 => lo plane

    for (int c = 0; c < 18; c++) {
        if (c + 1 < 18) {
            u32 sz; const unsigned char* s = chunk_src(c + 1, sz);
            u32 dst = sb + WOFF + ((c + 1) & 1) * 40960u;
            for (u32 r = tid * 16; r < sz; r += 8192) cp16(dst + r, s + r);
            asm volatile("cp.async.commit_group;");
            asm volatile("cp.async.wait_group 1;" ::: "memory");
        } else {
            asm volatile("cp.async.wait_group 0;" ::: "memory");
        }
        __syncthreads();

        if (c == 0 || c == 2 || c == 10) {
#pragma unroll
            for (int mt = 0; mt < 2; mt++)
#pragma unroll
                for (int nt = 0; nt < 8; nt++)
#pragma unroll
                    for (int q = 0; q < 4; q++) acc[mt][nt][q] = 0.f;
        }

        // ---- consume chunk c (32 k = 2 mma k-steps) ----
        const u32 wb = sb + WOFF + (c & 1) * 40960u;
        if (c < 10) {                                    // L0/L1: N=256, ntc=8
            const int lc = (c < 2) ? c : c - 2;
            const u32 bb0 = wb + (u32)ng * (64u * 80u) + brow80 + bksel + bplane * 20480u;
#pragma unroll
            for (int ks = 0; ks < 2; ks++) {
                const int kb = lc * 64 + ks * 32;
                u32 af[2][2][4];
                {
                    int arow = mg * 32 + (lane & 15);
                    int akb  = kb + ((lane >> 4) << 4);
#pragma unroll
                    for (int mt = 0; mt < 2; mt++) {
                        u32 ad = sb + aoff(arow + mt * 16, akb);
                        ldsm4(af[mt][0], ad);
                        ldsm4(af[mt][1], ad + ALO);
                    }
                }
                const u32 bks = bb0 + (u32)ks * 32u;
#pragma unroll
                for (int nt = 0; nt < 8; nt++) {
                    u32 b[4];
                    ldsm4(b, bks + (u32)nt * 640u);
                    MMA3(acc[0][nt], af[0], b);
                    MMA3(acc[1][nt], af[1], b);
                }
            }
        } else {                                         // L2: N=64, ntc=2
            const int lc = c - 10;
            const u32 bb0 = wb + (u32)ng * (16u * 80u) + brow80 + bksel + bplane * 5120u;
#pragma unroll
            for (int ks = 0; ks < 2; ks++) {
                const int kb = lc * 64 + ks * 32;
                u32 af[2][2][4];
                {
                    int arow = mg * 32 + (lane & 15);
                    int akb  = kb + ((lane >> 4) << 4);
#pragma unroll
                    for (int mt = 0; mt < 2; mt++) {
                        u32 ad = sb + aoff(arow + mt * 16, akb);
                        ldsm4(af[mt][0], ad);
                        ldsm4(af[mt][1], ad + ALO);
                    }
                }
                const u32 bks = bb0 + (u32)ks * 32u;
#pragma unroll
                for (int nt = 0; nt < 2; nt++) {
                    u32 b[4];
                    ldsm4(b, bks + (u32)nt * 640u);
                    MMA3(acc[0][nt], af[0], b);
                    MMA3(acc[1][nt], af[1], b);
                }
            }
        }
        __syncthreads();

        // ---- layer epilogues: softplus/JVP, write next activations ----
        if (c == 1 || c == 9) {
            const float* bs = bias + ((c == 1) ? 0 : 256);
#pragma unroll
            for (int mt = 0; mt < 2; mt++)
#pragma unroll
                for (int nt = 0; nt < 8; nt++) {
                    int n = ng * 64 + nt * 8 + c2;
                    float b0v = ev ? bs[n] : 0.f, b1v = ev ? bs[n + 1] : 0.f;
#pragma unroll
                    for (int h = 0; h < 2; h++) {
                        int row = mg * 32 + mt * 16 + g + h * 8;
                        float z0 = acc[mt][nt][2 * h]     + b0v;
                        float z1 = acc[mt][nt][2 * h + 1] + b1v;
                        float s0, h0, s1, h1;
                        actf(z0, s0, h0); actf(z1, s1, h1);
                        float su0 = __shfl_up_sync(0xffffffffu, s0, 4);
                        float su1 = __shfl_up_sync(0xffffffffu, s1, 4);
                        float v0 = ev ? h0 : su0 * z0;
                        float v1 = ev ? h1 : su1 * z1;
                        __nv_bfloat162 hp, lp;
                        hp.x = __float2bfloat16(v0); hp.y = __float2bfloat16(v1);
                        lp.x = __float2bfloat16(v0 - __bfloat162float(hp.x));
                        lp.y = __float2bfloat16(v1 - __bfloat162float(hp.y));
                        u32 o = aoff(row, 2 * n);
                        *(__nv_bfloat162*)(sm + o) = hp;
                        *(__nv_bfloat162*)(sm + ALO + o) = lp;
                    }
                }
            __syncthreads();
        }
    }

    // ---- final epilogue: dx (even rows) + divergence partials (odd rows) ----
    {
        const float* bs = bias + 512;
        float* dp = (float*)(sm + DIVOFF);
#pragma unroll
        for (int mt = 0; mt < 2; mt++)
#pragma unroll
            for (int h = 0; h < 2; h++) {
                int row = mg * 32 + mt * 16 + g + h * 8;
                int b = row >> 1;
                if (ev) {
#pragma unroll
                    for (int nt = 0; nt < 2; nt++) {
                        int n = ng * 16 + nt * 8 + c2;
                        out[(r0 + b) * 65 + n]     = acc[mt][nt][2 * h]     + bs[n];
                        out[(r0 + b) * 65 + n + 1] = acc[mt][nt][2 * h + 1] + bs[n + 1];
                    }
                } else {
                    float part = 0.f;
#pragma unroll
                    for (int nt = 0; nt < 2; nt++) {
                        int n = ng * 16 + nt * 8 + c2;
                        float2 ee = *(const float2*)&e[(r0 + b) * 64 + n];
                        part += acc[mt][nt][2 * h] * ee.x + acc[mt][nt][2 * h + 1] * ee.y;
                    }
                    dp[b * 16 + ng * 4 + (lane & 3)] = part;
                }
            }
    }
    __syncthreads();
    if (tid < 64) {
        const float* q = (const float*)(sm + DIVOFF) + tid * 16;
        float s = 0.f;
#pragma unroll
        for (int i = 0; i < 16; i++) s += q[i];
        out[(r0 + tid) * 65 + 64] = -s;
    }
}

// ---------------- launch ----------------
extern "C" void kernel_launch(void* const* d_in, const int* in_sizes, int n_in,
                              void* d_out, int out_size)
{
    const float* t  = (const float*)d_in[0];
    const float* y  = (const float*)d_in[1];
    const float* e  = (const float*)d_in[2];
    const float* W0 = (const float*)d_in[3];
    const float* b0 = (const float*)d_in[4];
    const float* W1 = (const float*)d_in[5];
    const float* b1 = (const float*)d_in[6];
    const float* W2 = (const float*)d_in[7];
    const float* b2 = (const float*)d_in[8];
    float* out = (float*)d_out;
    int B = in_sizes[1] / 65;

    cudaStreamCaptureStatus cs = cudaStreamCaptureStatusNone;
    cudaStreamIsCapturing((cudaStream_t)0, &cs);
    if (cs == cudaStreamCaptureStatusNone) {
        cudaFuncSetAttribute(odefunc_kernel,
                             cudaFuncAttributeMaxDynamicSharedMemorySize, SMEMSZ);
    }

    prep_kernel<<<256, 256>>>(t, W0, b0, W1, b1, W2, b2);
    odefunc_kernel<<<B / 64, 512, SMEMSZ>>>(y, e, out);
}

// round 13
// speedup vs baseline: 1.2812x; 1.2812x over previous
#include <cuda_runtime.h>
#include <cuda_fp16.h>
#include <cstdint>
typedef uint32_t u32;

// ---- smem byte map ----
#define ALO    65536u                 // A lo plane
#define WOFF   131072u                // 2 x 36864 weight slots
#define WSLOT  36864u
#define BIOFF  204800u
#define DIVOFF 207104u
#define SMEMSZ 211200u

// 9 ldmatrix-ready fp16 weight images (hi plane only):
// img0: W0 (256 rows x 64k = 144B/row) ; img1-4: W1 k-chunks ; img5-8: W2 k-chunks (64 rows)
static __device__ __align__(16) unsigned char gImg[221184];
static __device__ float gBias[576];

__global__ void prep_kernel(const float* __restrict__ t,
                            const float* __restrict__ W0, const float* __restrict__ b0,
                            const float* __restrict__ W1, const float* __restrict__ b1,
                            const float* __restrict__ W2, const float* __restrict__ b2)
{
    int n = blockIdx.x, x = threadIdx.x;         // n: out-neuron, x: k
    {   // W1 [256][257] -> images 1..4 (64 k each)
        float v = W1[n * 257 + x + 1];
        u32 off = WSLOT * (1u + (u32)(x >> 6)) + (u32)n * 144u + (u32)(x & 63) * 2u;
        *(__half*)(gImg + off) = __float2half_rn(v);
    }
    if (x < 64) {   // W0 [256][65] -> image 0
        *(__half*)(gImg + (u32)n * 144u + (u32)x * 2u) = __float2half_rn(W0[n * 65 + x + 1]);
    }
    if (n < 64) {   // W2 [64][257] -> images 5..8 (64 rows x 64 k, 9216B)
        float v = W2[n * 257 + x + 1];
        u32 off = 5u * WSLOT + (u32)(x >> 6) * 9216u + (u32)n * 144u + (u32)(x & 63) * 2u;
        *(__half*)(gImg + off) = __float2half_rn(v);
    }
    if (n == 0) {
        float tv = t[0];
        gBias[x] = b0[x] + tv * W0[x * 65];
        gBias[256 + x] = b1[x] + tv * W1[x * 257];
        if (x < 64) gBias[512 + x] = b2[x] + tv * W2[x * 257];
    }
}

// ---------------- helpers ----------------
__device__ __forceinline__ u32 s2u(const void* p) {
    u32 a; asm("{.reg .u64 t; cvta.to.shared.u64 t,%1; cvt.u32.u64 %0,t;}" : "=r"(a) : "l"(p)); return a;
}
__device__ __forceinline__ void cp16(u32 s, const void* g) {
    asm volatile("cp.async.cg.shared.global [%0],[%1],16;" :: "r"(s), "l"(g));
}
__device__ __forceinline__ void ldsm4(u32* r, u32 a) {
    asm volatile("ldmatrix.sync.aligned.m8n8.x4.shared.b16 {%0,%1,%2,%3},[%4];"
        : "=r"(r[0]), "=r"(r[1]), "=r"(r[2]), "=r"(r[3]) : "r"(a));
}
__device__ __forceinline__ void mma16816(float* c, const u32* a, const u32* b) {
    asm volatile("mma.sync.aligned.m16n8k16.row.col.f32.f16.f16.f32 "
        "{%0,%1,%2,%3},{%4,%5,%6,%7},{%8,%9},{%0,%1,%2,%3};"
        : "+f"(c[0]), "+f"(c[1]), "+f"(c[2]), "+f"(c[3])
        : "r"(a[0]), "r"(a[1]), "r"(a[2]), "r"(a[3]), "r"(b[0]), "r"(b[1]));
}
__device__ __forceinline__ void actf(float z, float& s, float& h) {
    float ea  = __expf(-fabsf(z));
    float inv = __fdividef(1.f, 1.f + ea);
    s = (z >= 0.f) ? inv : ea * inv;
    h = fmaxf(z, 0.f) + __logf(1.f + ea);
}
__device__ __forceinline__ const unsigned char* chunk_src(int i, u32& sz) {
    if (i < 5) { sz = 36864; return gImg + (u32)i * 36864u; }
    sz = 9216;  return gImg + 184320u + (u32)(i - 5) * 9216u;
}
// swizzled byte offset into activation plane: row stride 512B, 16B granule XOR
__device__ __forceinline__ u32 aoff(int row, int kb) {
    return (u32)row * 512u + ((((u32)kb >> 4) ^ (row & 7)) << 4) + (kb & 15);
}

__global__ void __launch_bounds__(512, 1)
odefunc_kernel(const float* __restrict__ y, const float* __restrict__ e,
               float* __restrict__ out)
{
    extern __shared__ char sm[];
    const u32 sb = s2u(sm);
    const int tid = threadIdx.x, lane = tid & 31, w = tid >> 5;
    const int mg = w >> 2, ng = w & 3;          // 4 x 4 warp grid
    const size_t r0 = (size_t)blockIdx.x * 64;

    // ---- stage inputs: row 2b = y_state, row 2b+1 = e; fp16 hi/lo planes ----
    for (int p = tid; p < 4096; p += 512) {
        int m = p >> 5, kp = p & 31, b = m >> 1;
        float v0, v1;
        if (m & 1) { v0 = e[(r0 + b) * 64 + 2 * kp]; v1 = e[(r0 + b) * 64 + 2 * kp + 1]; }
        else       { v0 = y[(r0 + b) * 65 + 2 * kp]; v1 = y[(r0 + b) * 65 + 2 * kp + 1]; }
        __half2 hp, lp;
        hp.x = __float2half_rn(v0); hp.y = __float2half_rn(v1);
        lp.x = __float2half_rn(v0 - __half2float(hp.x));
        lp.y = __float2half_rn(v1 - __half2float(hp.y));
        u32 o = aoff(m, kp * 4);
        *(__half2*)(sm + o) = hp;
        *(__half2*)(sm + ALO + o) = lp;
    }
    for (int i = tid; i < 576; i += 512) ((float*)(sm + BIOFF))[i] = gBias[i];

    // prime chunk 0
    { u32 sz; const unsigned char* s = chunk_src(0, sz);
      for (u32 r = tid * 16; r < sz; r += 8192) cp16(sb + WOFF + r, s + r);
      asm volatile("cp.async.commit_group;"); }

    float acc[2][8][4];
    const float* bias = (const float*)(sm + BIOFF);
    const int g = lane >> 2, c2 = (lane & 3) * 2;
    const bool ev = !(g & 1);

    // B ldsm.x4 lane address: lanes0-7 n+0..7 k0 | 8-15 n0..7 k+16B | 16-23 n+8 k0 | 24-31 n+8 k+16B
    const u32 bladdr = (u32)((lane & 7) + ((lane >> 4) & 1) * 8) * 144u
                     + (u32)((lane >> 3) & 1) * 16u;

    for (int c = 0; c < 9; c++) {
        asm volatile("cp.async.wait_group 0;" ::: "memory");
        __syncthreads();   // chunk c visible; all threads done consuming c-1 (slot reuse safe)
        if (c + 1 < 9) {
            u32 sz; const unsigned char* s = chunk_src(c + 1, sz);
            u32 dst = sb + WOFF + ((c + 1) & 1) * WSLOT;
            for (u32 r = tid * 16; r < sz; r += 8192) cp16(dst + r, s + r);
            asm volatile("cp.async.commit_group;");
        }

        if (c == 0 || c == 1 || c == 5) {
#pragma unroll
            for (int mt = 0; mt < 2; mt++)
#pragma unroll
                for (int nt = 0; nt < 8; nt++)
#pragma unroll
                    for (int q = 0; q < 4; q++) acc[mt][nt][q] = 0.f;
        }

        // ---- consume chunk c (64 k = 4 mma k-steps), 2-term fp16 split ----
        const u32 wb = sb + WOFF + (c & 1) * WSLOT;
        const int lc = (c == 0) ? 0 : ((c < 5) ? c - 1 : c - 5);
        if (c < 5) {                                     // L0/L1: N=256
            const u32 b0a = wb + (u32)ng * (64u * 144u) + bladdr;
#pragma unroll
            for (int ks = 0; ks < 4; ks++) {
                u32 af[2][2][4];
                {
                    int arow = mg * 32 + (lane & 15);
                    int akb  = lc * 128 + ks * 32 + ((lane >> 4) << 4);
#pragma unroll
                    for (int mt = 0; mt < 2; mt++) {
                        u32 ad = sb + aoff(arow + mt * 16, akb);
                        ldsm4(af[mt][0], ad);
                        ldsm4(af[mt][1], ad + ALO);
                    }
                }
                const u32 bks = b0a + (u32)ks * 32u;
#pragma unroll
                for (int np = 0; np < 4; np++) {
                    u32 b[4];
                    ldsm4(b, bks + (u32)np * 2304u);
#pragma unroll
                    for (int mt = 0; mt < 2; mt++) {
                        mma16816(acc[mt][2 * np],     af[mt][0], b);
                        mma16816(acc[mt][2 * np],     af[mt][1], b);
                        mma16816(acc[mt][2 * np + 1], af[mt][0], b + 2);
                        mma16816(acc[mt][2 * np + 1], af[mt][1], b + 2);
                    }
                }
            }
        } else {                                         // L2: N=64
            const u32 b0a = wb + (u32)ng * (16u * 144u) + bladdr;
#pragma unroll
            for (int ks = 0; ks < 4; ks++) {
                u32 af[2][2][4];
                {
                    int arow = mg * 32 + (lane & 15);
                    int akb  = lc * 128 + ks * 32 + ((lane >> 4) << 4);
#pragma unroll
                    for (int mt = 0; mt < 2; mt++) {
                        u32 ad = sb + aoff(arow + mt * 16, akb);
                        ldsm4(af[mt][0], ad);
                        ldsm4(af[mt][1], ad + ALO);
                    }
                }
                u32 b[4];
                ldsm4(b, b0a + (u32)ks * 32u);
#pragma unroll
                for (int mt = 0; mt < 2; mt++) {
                    mma16816(acc[mt][0], af[mt][0], b);
                    mma16816(acc[mt][0], af[mt][1], b);
                    mma16816(acc[mt][1], af[mt][0], b + 2);
                    mma16816(acc[mt][1], af[mt][1], b + 2);
                }
            }
        }

        // ---- layer epilogues: softplus/JVP, write next activations ----
        if (c == 0 || c == 4) {
            __syncthreads();   // all warps done ldsm-reading A planes before overwrite
            const float* bs = bias + ((c == 0) ? 0 : 256);
#pragma unroll
            for (int mt = 0; mt < 2; mt++)
#pragma unroll
                for (int nt = 0; nt < 8; nt++) {
                    int n = ng * 64 + nt * 8 + c2;
                    float b0v = ev ? bs[n] : 0.f, b1v = ev ? bs[n + 1] : 0.f;
#pragma unroll
                    for (int h = 0; h < 2; h++) {
                        int row = mg * 32 + mt * 16 + g + h * 8;
                        float z0 = acc[mt][nt][2 * h]     + b0v;
                        float z1 = acc[mt][nt][2 * h + 1] + b1v;
                        float s0 = 0.f, h0 = 0.f, s1 = 0.f, h1 = 0.f;
                        if (ev) { actf(z0, s0, h0); actf(z1, s1, h1); }  // odd lanes skip MUFU
                        float su0 = __shfl_up_sync(0xffffffffu, s0, 4);
                        float su1 = __shfl_up_sync(0xffffffffu, s1, 4);
                        float v0 = ev ? h0 : su0 * z0;
                        float v1 = ev ? h1 : su1 * z1;
                        __half2 hp, lp;
                        hp.x = __float2half_rn(v0); hp.y = __float2half_rn(v1);
                        lp.x = __float2half_rn(v0 - __half2float(hp.x));
                        lp.y = __float2half_rn(v1 - __half2float(hp.y));
                        u32 o = aoff(row, 2 * n);
                        *(__half2*)(sm + o) = hp;
                        *(__half2*)(sm + ALO + o) = lp;
                    }
                }
            // next chunk's MMA reads are ordered by the next iteration's top __syncthreads
        }
    }

    // ---- final epilogue: dx (even rows) + divergence partials (odd rows) ----
    {
        const float* bs = bias + 512;
        float* dp = (float*)(sm + DIVOFF);
#pragma unroll
        for (int mt = 0; mt < 2; mt++)
#pragma unroll
            for (int h = 0; h < 2; h++) {
                int row = mg * 32 + mt * 16 + g + h * 8;
                int b = row >> 1;
                if (ev) {
#pragma unroll
                    for (int nt = 0; nt < 2; nt++) {
                        int n = ng * 16 + nt * 8 + c2;
                        out[(r0 + b) * 65 + n]     = acc[mt][nt][2 * h]     + bs[n];
                        out[(r0 + b) * 65 + n + 1] = acc[mt][nt][2 * h + 1] + bs[n + 1];
                    }
                } else {
                    float part = 0.f;
#pragma unroll
                    for (int nt = 0; nt < 2; nt++) {
                        int n = ng * 16 + nt * 8 + c2;
                        float2 ee = *(const float2*)&e[(r0 + b) * 64 + n];
                        part += acc[mt][nt][2 * h] * ee.x + acc[mt][nt][2 * h + 1] * ee.y;
                    }
                    dp[b * 16 + ng * 4 + (lane & 3)] = part;
                }
            }
    }
    __syncthreads();
    if (tid < 64) {
        const float* q = (const float*)(sm + DIVOFF) + tid * 16;
        float s = 0.f;
#pragma unroll
        for (int i = 0; i < 16; i++) s += q[i];
        out[(r0 + tid) * 65 + 64] = -s;
    }
}

// ---------------- launch ----------------
extern "C" void kernel_launch(void* const* d_in, const int* in_sizes, int n_in,
                              void* d_out, int out_size)
{
    const float* t  = (const float*)d_in[0];
    const float* y  = (const float*)d_in[1];
    const float* e  = (const float*)d_in[2];
    const float* W0 = (const float*)d_in[3];
    const float* b0 = (const float*)d_in[4];
    const float* W1 = (const float*)d_in[5];
    const float* b1 = (const float*)d_in[6];
    const float* W2 = (const float*)d_in[7];
    const float* b2 = (const float*)d_in[8];
    float* out = (float*)d_out;
    int B = in_sizes[1] / 65;

    cudaStreamCaptureStatus cs = cudaStreamCaptureStatusNone;
    cudaStreamIsCapturing((cudaStream_t)0, &cs);
    if (cs == cudaStreamCaptureStatusNone) {
        cudaFuncSetAttribute(odefunc_kernel,
                             cudaFuncAttributeMaxDynamicSharedMemorySize, SMEMSZ);
    }

    prep_kernel<<<256, 256>>>(t, W0, b0, W1, b1, W2, b2);
    odefunc_kernel<<<B / 64, 512, SMEMSZ>>>(y, e, out);
}

// round 14
// speedup vs baseline: 1.3681x; 1.0678x over previous
#include <cuda_runtime.h>
#include <cuda_fp16.h>
#include <cstdint>
typedef uint32_t u32;

// ---- smem byte map (per 256-thread CTA, 32 batch rows, M=64) ----
#define ALO    32768u                 // A lo plane
#define WOFF   65536u                 // 2 x 20480 weight slots
#define WSLOT  20480u
#define BIOFF  106496u
#define DIVOFF 108800u
#define SMEMSZ 110848u

// 18 ldmatrix-ready fp16 weight images (32-k chunks, 80B rows):
// img0-1: W0 ; img2-9: W1 ; img10-17: W2 (64 rows, 5120B)
static __device__ __align__(16) unsigned char gImg[245760];
static __device__ float gBias[576];

__global__ void prep_kernel(const float* __restrict__ t,
                            const float* __restrict__ W0, const float* __restrict__ b0,
                            const float* __restrict__ W1, const float* __restrict__ b1,
                            const float* __restrict__ W2, const float* __restrict__ b2)
{
    int n = blockIdx.x, x = threadIdx.x;         // n: out-neuron, x: k
    {   // W1 [256][257] -> images 2..9 (32 k each)
        float v = W1[n * 257 + x + 1];
        u32 off = (2u + (u32)(x >> 5)) * 20480u + (u32)n * 80u + (u32)(x & 31) * 2u;
        *(__half*)(gImg + off) = __float2half_rn(v);
    }
    if (x < 64) {   // W0 [256][65] -> images 0..1
        u32 off = (u32)(x >> 5) * 20480u + (u32)n * 80u + (u32)(x & 31) * 2u;
        *(__half*)(gImg + off) = __float2half_rn(W0[n * 65 + x + 1]);
    }
    if (n < 64) {   // W2 [64][257] -> images 10..17 (64 rows x 32 k, 5120B)
        float v = W2[n * 257 + x + 1];
        u32 off = 204800u + (u32)(x >> 5) * 5120u + (u32)n * 80u + (u32)(x & 31) * 2u;
        *(__half*)(gImg + off) = __float2half_rn(v);
    }
    if (n == 0) {
        float tv = t[0];
        gBias[x] = b0[x] + tv * W0[x * 65];
        gBias[256 + x] = b1[x] + tv * W1[x * 257];
        if (x < 64) gBias[512 + x] = b2[x] + tv * W2[x * 257];
    }
}

// ---------------- helpers ----------------
__device__ __forceinline__ u32 s2u(const void* p) {
    u32 a; asm("{.reg .u64 t; cvta.to.shared.u64 t,%1; cvt.u32.u64 %0,t;}" : "=r"(a) : "l"(p)); return a;
}
__device__ __forceinline__ void cp16(u32 s, const void* g) {
    asm volatile("cp.async.cg.shared.global [%0],[%1],16;" :: "r"(s), "l"(g));
}
__device__ __forceinline__ void ldsm4(u32* r, u32 a) {
    asm volatile("ldmatrix.sync.aligned.m8n8.x4.shared.b16 {%0,%1,%2,%3},[%4];"
        : "=r"(r[0]), "=r"(r[1]), "=r"(r[2]), "=r"(r[3]) : "r"(a));
}
__device__ __forceinline__ void mma16816(float* c, const u32* a, const u32* b) {
    asm volatile("mma.sync.aligned.m16n8k16.row.col.f32.f16.f16.f32 "
        "{%0,%1,%2,%3},{%4,%5,%6,%7},{%8,%9},{%0,%1,%2,%3};"
        : "+f"(c[0]), "+f"(c[1]), "+f"(c[2]), "+f"(c[3])
        : "r"(a[0]), "r"(a[1]), "r"(a[2]), "r"(a[3]), "r"(b[0]), "r"(b[1]));
}
__device__ __forceinline__ void actf(float z, float& s, float& h) {
    float ea  = __expf(-fabsf(z));
    float inv = __fdividef(1.f, 1.f + ea);
    s = (z >= 0.f) ? inv : ea * inv;
    h = fmaxf(z, 0.f) + __logf(1.f + ea);
}
__device__ __forceinline__ const unsigned char* chunk_src(int i, u32& sz) {
    if (i < 10) { sz = 20480; return gImg + (u32)i * 20480u; }
    sz = 5120;  return gImg + 204800u + (u32)(i - 10) * 5120u;
}
// swizzled byte offset into activation plane: row stride 512B, 16B granule XOR
__device__ __forceinline__ u32 aoff(int row, int kb) {
    return (u32)row * 512u + ((((u32)kb >> 4) ^ (row & 7)) << 4) + (kb & 15);
}

__global__ void __launch_bounds__(256, 2)
odefunc_kernel(const float* __restrict__ y, const float* __restrict__ e,
               float* __restrict__ out)
{
    extern __shared__ char sm[];
    const u32 sb = s2u(sm);
    const int tid = threadIdx.x, lane = tid & 31, w = tid >> 5;
    const int mg = w >> 2, ng = w & 3;          // 2 x 4 warp grid
    const size_t r0 = (size_t)blockIdx.x * 32;

    // ---- stage inputs: row 2b = y_state, row 2b+1 = e; fp16 hi/lo planes ----
    for (int p = tid; p < 2048; p += 256) {
        int m = p >> 5, kp = p & 31, b = m >> 1;
        float v0, v1;
        if (m & 1) { v0 = e[(r0 + b) * 64 + 2 * kp]; v1 = e[(r0 + b) * 64 + 2 * kp + 1]; }
        else       { v0 = y[(r0 + b) * 65 + 2 * kp]; v1 = y[(r0 + b) * 65 + 2 * kp + 1]; }
        __half2 hp, lp;
        hp.x = __float2half_rn(v0); hp.y = __float2half_rn(v1);
        lp.x = __float2half_rn(v0 - __half2float(hp.x));
        lp.y = __float2half_rn(v1 - __half2float(hp.y));
        u32 o = aoff(m, kp * 4);
        *(__half2*)(sm + o) = hp;
        *(__half2*)(sm + ALO + o) = lp;
    }
    for (int i = tid; i < 576; i += 256) ((float*)(sm + BIOFF))[i] = gBias[i];

    // prime chunk 0
    { u32 sz; const unsigned char* s = chunk_src(0, sz);
      for (u32 r = tid * 16; r < sz; r += 4096) cp16(sb + WOFF + r, s + r);
      asm volatile("cp.async.commit_group;"); }

    float acc[2][8][4];
    const float* bias = (const float*)(sm + BIOFF);
    const int g = lane >> 2, c2 = (lane & 3) * 2;
    const bool ev = !(g & 1);

    // B ldsm.x4 lane address: lanes0-7 n0..7 k0 | 8-15 n0..7 +16B | 16-23 n8..15 k0 | 24-31 n8..15 +16B
    const u32 bladdr = (u32)((lane & 7) + ((lane >> 4) & 1) * 8) * 80u
                     + (u32)((lane >> 3) & 1) * 16u;

    for (int c = 0; c < 18; c++) {
        asm volatile("cp.async.wait_group 0;" ::: "memory");
        __syncthreads();   // chunk c visible; all threads done with slot before refill
        if (c + 1 < 18) {
            u32 sz; const unsigned char* s = chunk_src(c + 1, sz);
            u32 dst = sb + WOFF + ((c + 1) & 1) * WSLOT;
            for (u32 r = tid * 16; r < sz; r += 4096) cp16(dst + r, s + r);
            asm volatile("cp.async.commit_group;");
        }

        if (c == 0 || c == 2 || c == 10) {
#pragma unroll
            for (int mt = 0; mt < 2; mt++)
#pragma unroll
                for (int nt = 0; nt < 8; nt++)
#pragma unroll
                    for (int q = 0; q < 4; q++) acc[mt][nt][q] = 0.f;
        }

        // ---- consume chunk c (32 k = 2 mma k-steps), 2-term fp16 split ----
        const u32 wb = sb + WOFF + (c & 1) * WSLOT;
        const int lc = (c < 2) ? c : ((c < 10) ? c - 2 : c - 10);
        if (c < 10) {                                    // L0/L1: N=256
            const u32 b0a = wb + (u32)ng * (64u * 80u) + bladdr;
#pragma unroll
            for (int ks = 0; ks < 2; ks++) {
                u32 af[2][2][4];
                {
                    int arow = mg * 32 + (lane & 15);
                    int akb  = lc * 64 + ks * 32 + ((lane >> 4) << 4);
#pragma unroll
                    for (int mt = 0; mt < 2; mt++) {
                        u32 ad = sb + aoff(arow + mt * 16, akb);
                        ldsm4(af[mt][0], ad);
                        ldsm4(af[mt][1], ad + ALO);
                    }
                }
                const u32 bks = b0a + (u32)ks * 32u;
#pragma unroll
                for (int np = 0; np < 4; np++) {
                    u32 b[4];
                    ldsm4(b, bks + (u32)np * 1280u);
#pragma unroll
                    for (int mt = 0; mt < 2; mt++) {
                        mma16816(acc[mt][2 * np],     af[mt][0], b);
                        mma16816(acc[mt][2 * np],     af[mt][1], b);
                        mma16816(acc[mt][2 * np + 1], af[mt][0], b + 2);
                        mma16816(acc[mt][2 * np + 1], af[mt][1], b + 2);
                    }
                }
            }
        } else {                                         // L2: N=64
            const u32 b0a = wb + (u32)ng * (16u * 80u) + bladdr;
#pragma unroll
            for (int ks = 0; ks < 2; ks++) {
                u32 af[2][2][4];
                {
                    int arow = mg * 32 + (lane & 15);
                    int akb  = lc * 64 + ks * 32 + ((lane >> 4) << 4);
#pragma unroll
                    for (int mt = 0; mt < 2; mt++) {
                        u32 ad = sb + aoff(arow + mt * 16, akb);
                        ldsm4(af[mt][0], ad);
                        ldsm4(af[mt][1], ad + ALO);
                    }
                }
                u32 b[4];
                ldsm4(b, b0a + (u32)ks * 32u);
#pragma unroll
                for (int mt = 0; mt < 2; mt++) {
                    mma16816(acc[mt][0], af[mt][0], b);
                    mma16816(acc[mt][0], af[mt][1], b);
                    mma16816(acc[mt][1], af[mt][0], b + 2);
                    mma16816(acc[mt][1], af[mt][1], b + 2);
                }
            }
        }

        // ---- layer epilogues: softplus/JVP, write next activations ----
        if (c == 1 || c == 9) {
            __syncthreads();   // all warps done ldsm-reading A planes before overwrite
            const float* bs = bias + ((c == 1) ? 0 : 256);
#pragma unroll
            for (int mt = 0; mt < 2; mt++)
#pragma unroll
                for (int nt = 0; nt < 8; nt++) {
                    int n = ng * 64 + nt * 8 + c2;
                    float b0v = ev ? bs[n] : 0.f, b1v = ev ? bs[n + 1] : 0.f;
#pragma unroll
                    for (int h = 0; h < 2; h++) {
                        int row = mg * 32 + mt * 16 + g + h * 8;
                        float z0 = acc[mt][nt][2 * h]     + b0v;
                        float z1 = acc[mt][nt][2 * h + 1] + b1v;
                        float s0 = 0.f, h0 = 0.f, s1 = 0.f, h1 = 0.f;
                        if (ev) { actf(z0, s0, h0); actf(z1, s1, h1); }  // odd lanes skip MUFU
                        float su0 = __shfl_up_sync(0xffffffffu, s0, 4);
                        float su1 = __shfl_up_sync(0xffffffffu, s1, 4);
                        float v0 = ev ? h0 : su0 * z0;
                        float v1 = ev ? h1 : su1 * z1;
                        __half2 hp, lp;
                        hp.x = __float2half_rn(v0); hp.y = __float2half_rn(v1);
                        lp.x = __float2half_rn(v0 - __half2float(hp.x));
                        lp.y = __float2half_rn(v1 - __half2float(hp.y));
                        u32 o = aoff(row, 2 * n);
                        *(__half2*)(sm + o) = hp;
                        *(__half2*)(sm + ALO + o) = lp;
                    }
                }
            // next chunk's MMA reads are ordered by the next iteration's top __syncthreads
        }
    }

    // ---- final epilogue: dx (even rows) + divergence partials (odd rows) ----
    {
        const float* bs = bias + 512;
        float* dp = (float*)(sm + DIVOFF);
#pragma unroll
        for (int mt = 0; mt < 2; mt++)
#pragma unroll
            for (int h = 0; h < 2; h++) {
                int row = mg * 32 + mt * 16 + g + h * 8;
                int b = row >> 1;
                if (ev) {
#pragma unroll
                    for (int nt = 0; nt < 2; nt++) {
                        int n = ng * 16 + nt * 8 + c2;
                        out[(r0 + b) * 65 + n]     = acc[mt][nt][2 * h]     + bs[n];
                        out[(r0 + b) * 65 + n + 1] = acc[mt][nt][2 * h + 1] + bs[n + 1];
                    }
                } else {
                    float part = 0.f;
#pragma unroll
                    for (int nt = 0; nt < 2; nt++) {
                        int n = ng * 16 + nt * 8 + c2;
                        float2 ee = *(const float2*)&e[(r0 + b) * 64 + n];
                        part += acc[mt][nt][2 * h] * ee.x + acc[mt][nt][2 * h + 1] * ee.y;
                    }
                    dp[b * 16 + ng * 4 + (lane & 3)] = part;
                }
            }
    }
    __syncthreads();
    if (tid < 32) {
        const float* q = (const float*)(sm + DIVOFF) + tid * 16;
        float s = 0.f;
#pragma unroll
        for (int i = 0; i < 16; i++) s += q[i];
        out[(r0 + tid) * 65 + 64] = -s;
    }
}

// ---------------- launch ----------------
extern "C" void kernel_launch(void* const* d_in, const int* in_sizes, int n_in,
                              void* d_out, int out_size)
{
    const float* t  = (const float*)d_in[0];
    const float* y  = (const float*)d_in[1];
    const float* e  = (const float*)d_in[2];
    const float* W0 = (const float*)d_in[3];
    const float* b0 = (const float*)d_in[4];
    const float* W1 = (const float*)d_in[5];
    const float* b1 = (const float*)d_in[6];
    const float* W2 = (const float*)d_in[7];
    const float* b2 = (const float*)d_in[8];
    float* out = (float*)d_out;
    int B = in_sizes[1] / 65;

    cudaStreamCaptureStatus cs = cudaStreamCaptureStatusNone;
    cudaStreamIsCapturing((cudaStream_t)0, &cs);
    if (cs == cudaStreamCaptureStatusNone) {
        cudaFuncSetAttribute(odefunc_kernel,
                             cudaFuncAttributeMaxDynamicSharedMemorySize, SMEMSZ);
    }

    prep_kernel<<<256, 256>>>(t, W0, b0, W1, b1, W2, b2);
    odefunc_kernel<<<B / 32, 256, SMEMSZ>>>(y, e, out);
}

// round 15
// speedup vs baseline: 1.8324x; 1.3394x over previous
#include <cuda_runtime.h>
#include <cuda_fp16.h>
#include <cstdint>
typedef uint32_t u32;

// ---- smem byte map (per 256-thread CTA, 32 batch rows, M=64) ----
#define WOFF   32768u                 // 3 x 20480 weight ring
#define WSLOT  20480u
#define BIOFF  94208u
#define DIVOFF 96512u
#define SMEMSZ 98560u

// 18 ldmatrix-ready fp16 weight images (32-k chunks, 80B rows):
// img0-1: W0 ; img2-9: W1 ; img10-17: W2 (64 rows, 5120B)
static __device__ __align__(16) unsigned char gImg[245760];
static __device__ float gBias[576];

__global__ void prep_kernel(const float* __restrict__ t,
                            const float* __restrict__ W0, const float* __restrict__ b0,
                            const float* __restrict__ W1, const float* __restrict__ b1,
                            const float* __restrict__ W2, const float* __restrict__ b2)
{
    int n = blockIdx.x, x = threadIdx.x;         // n: out-neuron, x: k
    {   // W1 [256][257] -> images 2..9 (32 k each)
        float v = W1[n * 257 + x + 1];
        u32 off = (2u + (u32)(x >> 5)) * 20480u + (u32)n * 80u + (u32)(x & 31) * 2u;
        *(__half*)(gImg + off) = __float2half_rn(v);
    }
    if (x < 64) {   // W0 [256][65] -> images 0..1
        u32 off = (u32)(x >> 5) * 20480u + (u32)n * 80u + (u32)(x & 31) * 2u;
        *(__half*)(gImg + off) = __float2half_rn(W0[n * 65 + x + 1]);
    }
    if (n < 64) {   // W2 [64][257] -> images 10..17 (64 rows x 32 k, 5120B)
        float v = W2[n * 257 + x + 1];
        u32 off = 204800u + (u32)(x >> 5) * 5120u + (u32)n * 80u + (u32)(x & 31) * 2u;
        *(__half*)(gImg + off) = __float2half_rn(v);
    }
    if (n == 0) {
        float tv = t[0];
        gBias[x] = b0[x] + tv * W0[x * 65];
        gBias[256 + x] = b1[x] + tv * W1[x * 257];
        if (x < 64) gBias[512 + x] = b2[x] + tv * W2[x * 257];
    }
}

// ---------------- helpers ----------------
__device__ __forceinline__ u32 s2u(const void* p) {
    u32 a; asm("{.reg .u64 t; cvta.to.shared.u64 t,%1; cvt.u32.u64 %0,t;}" : "=r"(a) : "l"(p)); return a;
}
__device__ __forceinline__ void cp16(u32 s, const void* g) {
    asm volatile("cp.async.cg.shared.global [%0],[%1],16;" :: "r"(s), "l"(g));
}
__device__ __forceinline__ void ldsm4(u32* r, u32 a) {
    asm volatile("ldmatrix.sync.aligned.m8n8.x4.shared.b16 {%0,%1,%2,%3},[%4];"
        : "=r"(r[0]), "=r"(r[1]), "=r"(r[2]), "=r"(r[3]) : "r"(a));
}
__device__ __forceinline__ void mma16816(float* c, const u32* a, const u32* b) {
    asm volatile("mma.sync.aligned.m16n8k16.row.col.f32.f16.f16.f32 "
        "{%0,%1,%2,%3},{%4,%5,%6,%7},{%8,%9},{%0,%1,%2,%3};"
        : "+f"(c[0]), "+f"(c[1]), "+f"(c[2]), "+f"(c[3])
        : "r"(a[0]), "r"(a[1]), "r"(a[2]), "r"(a[3]), "r"(b[0]), "r"(b[1]));
}
__device__ __forceinline__ void actf(float z, float& s, float& h) {
    float ea  = __expf(-fabsf(z));
    float inv = __fdividef(1.f, 1.f + ea);
    s = (z >= 0.f) ? inv : ea * inv;
    h = fmaxf(z, 0.f) + __logf(1.f + ea);
}
__device__ __forceinline__ const unsigned char* chunk_src(int i, u32& sz) {
    if (i < 10) { sz = 20480; return gImg + (u32)i * 20480u; }
    sz = 5120;  return gImg + 204800u + (u32)(i - 10) * 5120u;
}
// swizzled byte offset into activation plane: row stride 512B, 16B granule XOR
__device__ __forceinline__ u32 aoff(int row, int kb) {
    return (u32)row * 512u + ((((u32)kb >> 4) ^ (row & 7)) << 4) + (kb & 15);
}

__global__ void __launch_bounds__(256, 2)
odefunc_kernel(const float* __restrict__ y, const float* __restrict__ e,
               float* __restrict__ out)
{
    extern __shared__ char sm[];
    const u32 sb = s2u(sm);
    const int tid = threadIdx.x, lane = tid & 31, w = tid >> 5;
    const int mg = w >> 2, ng = w & 3;          // 2 x 4 warp grid
    const size_t r0 = (size_t)blockIdx.x * 32;

    // ---- stage inputs: row 2b = y_state, row 2b+1 = e; fp16 (single plane) ----
    for (int p = tid; p < 2048; p += 256) {
        int m = p >> 5, kp = p & 31, b = m >> 1;
        float v0, v1;
        if (m & 1) { v0 = e[(r0 + b) * 64 + 2 * kp]; v1 = e[(r0 + b) * 64 + 2 * kp + 1]; }
        else       { v0 = y[(r0 + b) * 65 + 2 * kp]; v1 = y[(r0 + b) * 65 + 2 * kp + 1]; }
        __half2 hp;
        hp.x = __float2half_rn(v0); hp.y = __float2half_rn(v1);
        *(__half2*)(sm + aoff(m, kp * 4)) = hp;
    }
    for (int i = tid; i < 576; i += 256) ((float*)(sm + BIOFF))[i] = gBias[i];

    // prime chunks 0 and 1 (separate commit groups)
#pragma unroll
    for (int pc = 0; pc < 2; pc++) {
        u32 sz; const unsigned char* s = chunk_src(pc, sz);
        u32 dst = sb + WOFF + (u32)pc * WSLOT;
        for (u32 r = tid * 16; r < sz; r += 4096) cp16(dst + r, s + r);
        asm volatile("cp.async.commit_group;");
    }

    float acc[2][8][4];
    const float* bias = (const float*)(sm + BIOFF);
    const int g = lane >> 2, c2 = (lane & 3) * 2;
    const bool ev = !(g & 1);

    // B ldsm.x4 lane address: lanes0-7 n0..7 k0 | 8-15 n0..7 +16B | 16-23 n8..15 k0 | 24-31 n8..15 +16B
    const u32 bladdr = (u32)((lane & 7) + ((lane >> 4) & 1) * 8) * 80u
                     + (u32)((lane >> 3) & 1) * 16u;

    int slot = 0, nslot = 2;   // slot of chunk c ; slot for chunk c+2
    for (int c = 0; c < 18; c++) {
        if (c < 16) asm volatile("cp.async.wait_group 1;" ::: "memory");
        else        asm volatile("cp.async.wait_group 0;" ::: "memory");
        __syncthreads();   // chunk c visible; all warps done reading slot being refilled
        if (c + 2 < 18) {
            u32 sz; const unsigned char* s = chunk_src(c + 2, sz);
            u32 dst = sb + WOFF + (u32)nslot * WSLOT;
            for (u32 r = tid * 16; r < sz; r += 4096) cp16(dst + r, s + r);
            asm volatile("cp.async.commit_group;");
        }

        if (c == 0 || c == 2 || c == 10) {
#pragma unroll
            for (int mt = 0; mt < 2; mt++)
#pragma unroll
                for (int nt = 0; nt < 8; nt++)
#pragma unroll
                    for (int q = 0; q < 4; q++) acc[mt][nt][q] = 0.f;
        }

        // ---- consume chunk c (32 k = 2 mma k-steps), pure fp16 ----
        const u32 wb = sb + WOFF + (u32)slot * WSLOT;
        const int lc = (c < 2) ? c : ((c < 10) ? c - 2 : c - 10);
        if (c < 10) {                                    // L0/L1: N=256
            const u32 b0a = wb + (u32)ng * (64u * 80u) + bladdr;
#pragma unroll
            for (int ks = 0; ks < 2; ks++) {
                u32 af[2][4];
                {
                    int arow = mg * 32 + (lane & 15);
                    int akb  = lc * 64 + ks * 32 + ((lane >> 4) << 4);
#pragma unroll
                    for (int mt = 0; mt < 2; mt++)
                        ldsm4(af[mt], sb + aoff(arow + mt * 16, akb));
                }
                const u32 bks = b0a + (u32)ks * 32u;
#pragma unroll
                for (int np = 0; np < 4; np++) {
                    u32 b[4];
                    ldsm4(b, bks + (u32)np * 1280u);
#pragma unroll
                    for (int mt = 0; mt < 2; mt++) {
                        mma16816(acc[mt][2 * np],     af[mt], b);
                        mma16816(acc[mt][2 * np + 1], af[mt], b + 2);
                    }
                }
            }
        } else {                                         // L2: N=64
            const u32 b0a = wb + (u32)ng * (16u * 80u) + bladdr;
#pragma unroll
            for (int ks = 0; ks < 2; ks++) {
                u32 af[2][4];
                {
                    int arow = mg * 32 + (lane & 15);
                    int akb  = lc * 64 + ks * 32 + ((lane >> 4) << 4);
#pragma unroll
                    for (int mt = 0; mt < 2; mt++)
                        ldsm4(af[mt], sb + aoff(arow + mt * 16, akb));
                }
                u32 b[4];
                ldsm4(b, b0a + (u32)ks * 32u);
#pragma unroll
                for (int mt = 0; mt < 2; mt++) {
                    mma16816(acc[mt][0], af[mt], b);
                    mma16816(acc[mt][1], af[mt], b + 2);
                }
            }
        }
        slot = (slot == 2) ? 0 : slot + 1;
        nslot = (nslot == 2) ? 0 : nslot + 1;

        // ---- layer epilogues: softplus/JVP, write next activations ----
        if (c == 1 || c == 9) {
            __syncthreads();   // all warps done ldsm-reading A plane before overwrite
            const float* bs = bias + ((c == 1) ? 0 : 256);
#pragma unroll
            for (int mt = 0; mt < 2; mt++)
#pragma unroll
                for (int nt = 0; nt < 8; nt++) {
                    int n = ng * 64 + nt * 8 + c2;
                    float b0v = ev ? bs[n] : 0.f, b1v = ev ? bs[n + 1] : 0.f;
#pragma unroll
                    for (int h = 0; h < 2; h++) {
                        int row = mg * 32 + mt * 16 + g + h * 8;
                        float z0 = acc[mt][nt][2 * h]     + b0v;
                        float z1 = acc[mt][nt][2 * h + 1] + b1v;
                        float s0 = 0.f, h0 = 0.f, s1 = 0.f, h1 = 0.f;
                        if (ev) { actf(z0, s0, h0); actf(z1, s1, h1); }  // odd lanes skip MUFU
                        float su0 = __shfl_up_sync(0xffffffffu, s0, 4);
                        float su1 = __shfl_up_sync(0xffffffffu, s1, 4);
                        float v0 = ev ? h0 : su0 * z0;
                        float v1 = ev ? h1 : su1 * z1;
                        __half2 hp;
                        hp.x = __float2half_rn(v0); hp.y = __float2half_rn(v1);
                        *(__half2*)(sm + aoff(row, 2 * n)) = hp;
                    }
                }
            // next chunk's MMA reads are ordered by the next iteration's top __syncthreads
        }
    }

    // ---- final epilogue: dx (even rows) + divergence partials (odd rows) ----
    {
        const float* bs = bias + 512;
        float* dp = (float*)(sm + DIVOFF);
#pragma unroll
        for (int mt = 0; mt < 2; mt++)
#pragma unroll
            for (int h = 0; h < 2; h++) {
                int row = mg * 32 + mt * 16 + g + h * 8;
                int b = row >> 1;
                if (ev) {
#pragma unroll
                    for (int nt = 0; nt < 2; nt++) {
                        int n = ng * 16 + nt * 8 + c2;
                        out[(r0 + b) * 65 + n]     = acc[mt][nt][2 * h]     + bs[n];
                        out[(r0 + b) * 65 + n + 1] = acc[mt][nt][2 * h + 1] + bs[n + 1];
                    }
                } else {
                    float part = 0.f;
#pragma unroll
                    for (int nt = 0; nt < 2; nt++) {
                        int n = ng * 16 + nt * 8 + c2;
                        float2 ee = *(const float2*)&e[(r0 + b) * 64 + n];
                        part += acc[mt][nt][2 * h] * ee.x + acc[mt][nt][2 * h + 1] * ee.y;
                    }
                    dp[b * 16 + ng * 4 + (lane & 3)] = part;
                }
            }
    }
    __syncthreads();
    if (tid < 32) {
        const float* q = (const float*)(sm + DIVOFF) + tid * 16;
        float s = 0.f;
#pragma unroll
        for (int i = 0; i < 16; i++) s += q[i];
        out[(r0 + tid) * 65 + 64] = -s;
    }
}

// ---------------- launch ----------------
extern "C" void kernel_launch(void* const* d_in, const int* in_sizes, int n_in,
                              void* d_out, int out_size)
{
    const float* t  = (const float*)d_in[0];
    const float* y  = (const float*)d_in[1];
    const float* e  = (const float*)d_in[2];
    const float* W0 = (const float*)d_in[3];
    const float* b0 = (const float*)d_in[4];
    const float* W1 = (const float*)d_in[5];
    const float* b1 = (const float*)d_in[6];
    const float* W2 = (const float*)d_in[7];
    const float* b2 = (const float*)d_in[8];
    float* out = (float*)d_out;
    int B = in_sizes[1] / 65;

    cudaStreamCaptureStatus cs = cudaStreamCaptureStatusNone;
    cudaStreamIsCapturing((cudaStream_t)0, &cs);
    if (cs == cudaStreamCaptureStatusNone) {
        cudaFuncSetAttribute(odefunc_kernel,
                             cudaFuncAttributeMaxDynamicSharedMemorySize, SMEMSZ);
    }

    prep_kernel<<<256, 256>>>(t, W0, b0, W1, b1, W2, b2);
    odefunc_kernel<<<B / 32, 256, SMEMSZ>>>(y, e, out);
}

// round 16
// speedup vs baseline: 1.9773x; 1.0790x over previous
#include <cuda_runtime.h>
#include <cuda_fp16.h>
#include <cstdint>
typedef uint32_t u32;

// ---- smem byte map (per 256-thread CTA, 32 batch rows, M=64) ----
#define WOFF   32768u                 // 2 x 36864 weight ring
#define WSLOT  36864u
#define BIOFF  106496u
#define DIVOFF 108800u
#define SMEMSZ 110848u

// 9 ldmatrix-ready fp16 weight images (64-k chunks, 144B rows):
// img0: W0 (256 rows) ; img1-4: W1 ; img5-8: W2 (64 rows, 9216B)
static __device__ __align__(16) unsigned char gImg[221184];
static __device__ float gBias[576];

__global__ void prep_kernel(const float* __restrict__ t,
                            const float* __restrict__ W0, const float* __restrict__ b0,
                            const float* __restrict__ W1, const float* __restrict__ b1,
                            const float* __restrict__ W2, const float* __restrict__ b2)
{
    int n = blockIdx.x, x = threadIdx.x;         // n: out-neuron, x: k
    {   // W1 [256][257] -> images 1..4 (64 k each)
        float v = W1[n * 257 + x + 1];
        u32 off = 36864u * (1u + (u32)(x >> 6)) + (u32)n * 144u + (u32)(x & 63) * 2u;
        *(__half*)(gImg + off) = __float2half_rn(v);
    }
    if (x < 64) {   // W0 [256][65] -> image 0
        *(__half*)(gImg + (u32)n * 144u + (u32)x * 2u) = __float2half_rn(W0[n * 65 + x + 1]);
    }
    if (n < 64) {   // W2 [64][257] -> images 5..8 (64 rows x 64 k, 9216B)
        float v = W2[n * 257 + x + 1];
        u32 off = 184320u + (u32)(x >> 6) * 9216u + (u32)n * 144u + (u32)(x & 63) * 2u;
        *(__half*)(gImg + off) = __float2half_rn(v);
    }
    if (n == 0) {
        float tv = t[0];
        gBias[x] = b0[x] + tv * W0[x * 65];
        gBias[256 + x] = b1[x] + tv * W1[x * 257];
        if (x < 64) gBias[512 + x] = b2[x] + tv * W2[x * 257];
    }
}

// ---------------- helpers ----------------
__device__ __forceinline__ u32 s2u(const void* p) {
    u32 a; asm("{.reg .u64 t; cvta.to.shared.u64 t,%1; cvt.u32.u64 %0,t;}" : "=r"(a) : "l"(p)); return a;
}
__device__ __forceinline__ void cp16(u32 s, const void* g) {
    asm volatile("cp.async.cg.shared.global [%0],[%1],16;" :: "r"(s), "l"(g));
}
__device__ __forceinline__ void ldsm4(u32* r, u32 a) {
    asm volatile("ldmatrix.sync.aligned.m8n8.x4.shared.b16 {%0,%1,%2,%3},[%4];"
        : "=r"(r[0]), "=r"(r[1]), "=r"(r[2]), "=r"(r[3]) : "r"(a));
}
__device__ __forceinline__ void mma16816(float* c, const u32* a, const u32* b) {
    asm volatile("mma.sync.aligned.m16n8k16.row.col.f32.f16.f16.f32 "
        "{%0,%1,%2,%3},{%4,%5,%6,%7},{%8,%9},{%0,%1,%2,%3};"
        : "+f"(c[0]), "+f"(c[1]), "+f"(c[2]), "+f"(c[3])
        : "r"(a[0]), "r"(a[1]), "r"(a[2]), "r"(a[3]), "r"(b[0]), "r"(b[1]));
}
__device__ __forceinline__ void actf(float z, float& s, float& h) {
    float ea  = __expf(-fabsf(z));
    float inv = __fdividef(1.f, 1.f + ea);
    s = (z >= 0.f) ? inv : ea * inv;
    h = fmaxf(z, 0.f) + __logf(1.f + ea);
}
__device__ __forceinline__ const unsigned char* chunk_src(int i, u32& sz) {
    if (i < 5) { sz = 36864; return gImg + (u32)i * 36864u; }
    sz = 9216;  return gImg + 184320u + (u32)(i - 5) * 9216u;
}
// swizzled byte offset into activation plane: row stride 512B, 16B granule XOR
__device__ __forceinline__ u32 aoff(int row, int kb) {
    return (u32)row * 512u + ((((u32)kb >> 4) ^ (row & 7)) << 4) + (kb & 15);
}

__global__ void __launch_bounds__(256, 2)
odefunc_kernel(const float* __restrict__ y, const float* __restrict__ e,
               float* __restrict__ out)
{
    extern __shared__ char sm[];
    const u32 sb = s2u(sm);
    const int tid = threadIdx.x, lane = tid & 31, w = tid >> 5;
    const int mg = w >> 2, ng = w & 3;          // 2 x 4 warp grid
    const size_t r0 = (size_t)blockIdx.x * 32;

    // ---- stage inputs: row 2b = y_state, row 2b+1 = e; fp16 (single plane) ----
    for (int p = tid; p < 2048; p += 256) {
        int m = p >> 5, kp = p & 31, b = m >> 1;
        float v0, v1;
        if (m & 1) { v0 = e[(r0 + b) * 64 + 2 * kp]; v1 = e[(r0 + b) * 64 + 2 * kp + 1]; }
        else       { v0 = y[(r0 + b) * 65 + 2 * kp]; v1 = y[(r0 + b) * 65 + 2 * kp + 1]; }
        __half2 hp;
        hp.x = __float2half_rn(v0); hp.y = __float2half_rn(v1);
        *(__half2*)(sm + aoff(m, kp * 4)) = hp;
    }
    for (int i = tid; i < 576; i += 256) ((float*)(sm + BIOFF))[i] = gBias[i];

    // prime chunk 0 (slot 0)
    { u32 sz; const unsigned char* s = chunk_src(0, sz);
      for (u32 r = tid * 16; r < sz; r += 4096) cp16(sb + WOFF + r, s + r);
      asm volatile("cp.async.commit_group;"); }

    float acc[2][8][4];
    const float* bias = (const float*)(sm + BIOFF);
    const int g = lane >> 2, c2 = (lane & 3) * 2;
    const bool ev = !(g & 1);

    // B ldsm.x4 lane address: 144B weight rows
    const u32 bladdr = (u32)((lane & 7) + ((lane >> 4) & 1) * 8) * 144u
                     + (u32)((lane >> 3) & 1) * 16u;
    // A ldsm row/k components
    const int arow0 = mg * 32 + (lane & 15);
    const int aksel = (lane >> 4) << 4;

    for (int c = 0; c < 9; c++) {
        asm volatile("cp.async.wait_group 0;" ::: "memory");
        __syncthreads();   // chunk c visible; all warps done with the slot being refilled
        if (c + 1 < 9) {
            u32 sz; const unsigned char* s = chunk_src(c + 1, sz);
            u32 dst = sb + WOFF + (u32)((c + 1) & 1) * WSLOT;
            for (u32 r = tid * 16; r < sz; r += 4096) cp16(dst + r, s + r);
            asm volatile("cp.async.commit_group;");
        }

        if (c == 0 || c == 1 || c == 5) {
#pragma unroll
            for (int mt = 0; mt < 2; mt++)
#pragma unroll
                for (int nt = 0; nt < 8; nt++)
#pragma unroll
                    for (int q = 0; q < 4; q++) acc[mt][nt][q] = 0.f;
        }

        // ---- consume chunk c (64 k = 4 mma k-steps), pure fp16 ----
        const u32 wb = sb + WOFF + (u32)(c & 1) * WSLOT;
        const int lc = (c == 0) ? 0 : ((c < 5) ? c - 1 : c - 5);
        if (c < 5) {                                     // L0/L1: N=256
            const u32 b0a = wb + (u32)ng * 9216u + bladdr;
#pragma unroll
            for (int ks = 0; ks < 4; ks++) {
                u32 af[2][4];
                {
                    int akb = lc * 128 + ks * 32 + aksel;
#pragma unroll
                    for (int mt = 0; mt < 2; mt++)
                        ldsm4(af[mt], sb + aoff(arow0 + mt * 16, akb));
                }
                const u32 bks = b0a + (u32)ks * 32u;
#pragma unroll
                for (int np = 0; np < 4; np++) {
                    u32 b[4];
                    ldsm4(b, bks + (u32)np * 2304u);
#pragma unroll
                    for (int mt = 0; mt < 2; mt++) {
                        mma16816(acc[mt][2 * np],     af[mt], b);
                        mma16816(acc[mt][2 * np + 1], af[mt], b + 2);
                    }
                }
            }
        } else {                                         // L2: N=64
            const u32 b0a = wb + (u32)ng * 2304u + bladdr;
#pragma unroll
            for (int ks = 0; ks < 4; ks++) {
                u32 af[2][4];
                {
                    int akb = lc * 128 + ks * 32 + aksel;
#pragma unroll
                    for (int mt = 0; mt < 2; mt++)
                        ldsm4(af[mt], sb + aoff(arow0 + mt * 16, akb));
                }
                u32 b[4];
                ldsm4(b, b0a + (u32)ks * 32u);
#pragma unroll
                for (int mt = 0; mt < 2; mt++) {
                    mma16816(acc[mt][0], af[mt], b);
                    mma16816(acc[mt][1], af[mt], b + 2);
                }
            }
        }

        // ---- layer epilogues: softplus/JVP, write next activations ----
        if (c == 0 || c == 4) {
            __syncthreads();   // all warps done ldsm-reading A plane before overwrite
            const float* bs = bias + ((c == 0) ? 0 : 256);
#pragma unroll
            for (int mt = 0; mt < 2; mt++)
#pragma unroll
                for (int nt = 0; nt < 8; nt++) {
                    int n = ng * 64 + nt * 8 + c2;
                    float b0v = ev ? bs[n] : 0.f, b1v = ev ? bs[n + 1] : 0.f;
#pragma unroll
                    for (int h = 0; h < 2; h++) {
                        int row = mg * 32 + mt * 16 + g + h * 8;
                        float z0 = acc[mt][nt][2 * h]     + b0v;
                        float z1 = acc[mt][nt][2 * h + 1] + b1v;
                        float s0 = 0.f, h0 = 0.f, s1 = 0.f, h1 = 0.f;
                        if (ev) { actf(z0, s0, h0); actf(z1, s1, h1); }  // odd lanes skip MUFU
                        float su0 = __shfl_up_sync(0xffffffffu, s0, 4);
                        float su1 = __shfl_up_sync(0xffffffffu, s1, 4);
                        float v0 = ev ? h0 : su0 * z0;
                        float v1 = ev ? h1 : su1 * z1;
                        __half2 hp;
                        hp.x = __float2half_rn(v0); hp.y = __float2half_rn(v1);
                        *(__half2*)(sm + aoff(row, 2 * n)) = hp;
                    }
                }
            // next chunk's MMA reads are ordered by the next iteration's top __syncthreads
        }
    }

    // ---- final epilogue: dx (even rows) + divergence partials (odd rows) ----
    {
        const float* bs = bias + 512;
        float* dp = (float*)(sm + DIVOFF);
#pragma unroll
        for (int mt = 0; mt < 2; mt++)
#pragma unroll
            for (int h = 0; h < 2; h++) {
                int row = mg * 32 + mt * 16 + g + h * 8;
                int b = row >> 1;
                if (ev) {
#pragma unroll
                    for (int nt = 0; nt < 2; nt++) {
                        int n = ng * 16 + nt * 8 + c2;
                        out[(r0 + b) * 65 + n]     = acc[mt][nt][2 * h]     + bs[n];
                        out[(r0 + b) * 65 + n + 1] = acc[mt][nt][2 * h + 1] + bs[n + 1];
                    }
                } else {
                    float part = 0.f;
#pragma unroll
                    for (int nt = 0; nt < 2; nt++) {
                        int n = ng * 16 + nt * 8 + c2;
                        float2 ee = *(const float2*)&e[(r0 + b) * 64 + n];
                        part += acc[mt][nt][2 * h] * ee.x + acc[mt][nt][2 * h + 1] * ee.y;
                    }
                    dp[b * 16 + ng * 4 + (lane & 3)] = part;
                }
            }
    }
    __syncthreads();
    if (tid < 32) {
        const float* q = (const float*)(sm + DIVOFF) + tid * 16;
        float s = 0.f;
#pragma unroll
        for (int i = 0; i < 16; i++) s += q[i];
        out[(r0 + tid) * 65 + 64] = -s;
    }
}

// ---------------- launch ----------------
extern "C" void kernel_launch(void* const* d_in, const int* in_sizes, int n_in,
                              void* d_out, int out_size)
{
    const float* t  = (const float*)d_in[0];
    const float* y  = (const float*)d_in[1];
    const float* e  = (const float*)d_in[2];
    const float* W0 = (const float*)d_in[3];
    const float* b0 = (const float*)d_in[4];
    const float* W1 = (const float*)d_in[5];
    const float* b1 = (const float*)d_in[6];
    const float* W2 = (const float*)d_in[7];
    const float* b2 = (const float*)d_in[8];
    float* out = (float*)d_out;
    int B = in_sizes[1] / 65;

    cudaStreamCaptureStatus cs = cudaStreamCaptureStatusNone;
    cudaStreamIsCapturing((cudaStream_t)0, &cs);
    if (cs == cudaStreamCaptureStatusNone) {
        cudaFuncSetAttribute(odefunc_kernel,
                             cudaFuncAttributeMaxDynamicSharedMemorySize, SMEMSZ);
    }

    prep_kernel<<<256, 256>>>(t, W0, b0, W1, b1, W2, b2);
    odefunc_kernel<<<B / 32, 256, SMEMSZ>>>(y, e, out);
}

// round 17
// speedup vs baseline: 2.2986x; 1.1625x over previous
#include <cuda_runtime.h>
#include <cuda_fp16.h>
#include <cstdint>
typedef uint32_t u32;

// ---- smem byte map (per 256-thread CTA, 32 batch rows, M=64) ----
#define WOFF   32768u                 // 2 x 36864 weight ring
#define WSLOT  36864u
#define BIOFF  106496u
#define DIVOFF 108800u
#define SMEMSZ 110848u

// 9 ldmatrix-ready fp16 weight images (64-k chunks, 144B rows):
// img0: W0 (256 rows) ; img1-4: W1 ; img5-8: W2 (64 rows, 9216B)
static __device__ __align__(16) unsigned char gImg[221184];
static __device__ float gBias[576];

__global__ void prep_kernel(const float* __restrict__ t,
                            const float* __restrict__ W0, const float* __restrict__ b0,
                            const float* __restrict__ W1, const float* __restrict__ b1,
                            const float* __restrict__ W2, const float* __restrict__ b2)
{
    int n = blockIdx.x, x = threadIdx.x;         // n: out-neuron, x: k
    {   // W1 [256][257] -> images 1..4 (64 k each)
        float v = W1[n * 257 + x + 1];
        u32 off = 36864u * (1u + (u32)(x >> 6)) + (u32)n * 144u + (u32)(x & 63) * 2u;
        *(__half*)(gImg + off) = __float2half_rn(v);
    }
    if (x < 64) {   // W0 [256][65] -> image 0
        *(__half*)(gImg + (u32)n * 144u + (u32)x * 2u) = __float2half_rn(W0[n * 65 + x + 1]);
    }
    if (n < 64) {   // W2 [64][257] -> images 5..8 (64 rows x 64 k, 9216B)
        float v = W2[n * 257 + x + 1];
        u32 off = 184320u + (u32)(x >> 6) * 9216u + (u32)n * 144u + (u32)(x & 63) * 2u;
        *(__half*)(gImg + off) = __float2half_rn(v);
    }
    if (n == 0) {
        float tv = t[0];
        gBias[x] = b0[x] + tv * W0[x * 65];
        gBias[256 + x] = b1[x] + tv * W1[x * 257];
        if (x < 64) gBias[512 + x] = b2[x] + tv * W2[x * 257];
    }
}

// ---------------- helpers ----------------
__device__ __forceinline__ u32 s2u(const void* p) {
    u32 a; asm("{.reg .u64 t; cvta.to.shared.u64 t,%1; cvt.u32.u64 %0,t;}" : "=r"(a) : "l"(p)); return a;
}
__device__ __forceinline__ void cp16(u32 s, const void* g) {
    asm volatile("cp.async.cg.shared.global [%0],[%1],16;" :: "r"(s), "l"(g));
}
__device__ __forceinline__ void ldsm4(u32* r, u32 a) {
    asm volatile("ldmatrix.sync.aligned.m8n8.x4.shared.b16 {%0,%1,%2,%3},[%4];"
        : "=r"(r[0]), "=r"(r[1]), "=r"(r[2]), "=r"(r[3]) : "r"(a));
}
__device__ __forceinline__ void mma16816(float* c, const u32* a, const u32* b) {
    asm volatile("mma.sync.aligned.m16n8k16.row.col.f32.f16.f16.f32 "
        "{%0,%1,%2,%3},{%4,%5,%6,%7},{%8,%9},{%0,%1,%2,%3};"
        : "+f"(c[0]), "+f"(c[1]), "+f"(c[2]), "+f"(c[3])
        : "r"(a[0]), "r"(a[1]), "r"(a[2]), "r"(a[3]), "r"(b[0]), "r"(b[1]));
}
__device__ __forceinline__ void actf(float z, float& s, float& h) {
    float ea  = __expf(-fabsf(z));
    float inv = __fdividef(1.f, 1.f + ea);
    s = (z >= 0.f) ? inv : ea * inv;
    h = fmaxf(z, 0.f) + __logf(1.f + ea);
}
__device__ __forceinline__ const unsigned char* chunk_src(int i, u32& sz) {
    if (i < 5) { sz = 36864; return gImg + (u32)i * 36864u; }
    sz = 9216;  return gImg + 184320u + (u32)(i - 5) * 9216u;
}
// swizzled byte offset into activation plane: row stride 512B, 16B granule XOR
__device__ __forceinline__ u32 aoff(int row, int kb) {
    return (u32)row * 512u + ((((u32)kb >> 4) ^ (row & 7)) << 4) + (kb & 15);
}

__global__ void __launch_bounds__(256, 2)
odefunc_kernel(const float* __restrict__ y, const float* __restrict__ e,
               float* __restrict__ out)
{
    extern __shared__ char sm[];
    const u32 sb = s2u(sm);
    const int tid = threadIdx.x, lane = tid & 31, w = tid >> 5;
    const int mg = w >> 2, ng = w & 3;          // 2 x 4 warp grid
    const size_t r0 = (size_t)blockIdx.x * 32;

    // ---- stage inputs: row 2b = y_state, row 2b+1 = e; fp16 (single plane) ----
    for (int p = tid; p < 2048; p += 256) {
        int m = p >> 5, kp = p & 31, b = m >> 1;
        float v0, v1;
        if (m & 1) { v0 = e[(r0 + b) * 64 + 2 * kp]; v1 = e[(r0 + b) * 64 + 2 * kp + 1]; }
        else       { v0 = y[(r0 + b) * 65 + 2 * kp]; v1 = y[(r0 + b) * 65 + 2 * kp + 1]; }
        __half2 hp;
        hp.x = __float2half_rn(v0); hp.y = __float2half_rn(v1);
        *(__half2*)(sm + aoff(m, kp * 4)) = hp;
    }
    for (int i = tid; i < 576; i += 256) ((float*)(sm + BIOFF))[i] = gBias[i];

    // prime chunk 0 (slot 0)
    { u32 sz; const unsigned char* s = chunk_src(0, sz);
      for (u32 r = tid * 16; r < sz; r += 4096) cp16(sb + WOFF + r, s + r);
      asm volatile("cp.async.commit_group;"); }

    float acc[2][8][4];
    const float* bias = (const float*)(sm + BIOFF);
    const int g = lane >> 2, c2 = (lane & 3) * 2;
    const bool ev = !(g & 1);

    // B ldsm.x4 lane address: 144B weight rows
    const u32 bladdr = (u32)((lane & 7) + ((lane >> 4) & 1) * 8) * 144u
                     + (u32)((lane >> 3) & 1) * 16u;
    // A ldsm row/k components
    const int arow0 = mg * 32 + (lane & 15);
    const int aksel = (lane >> 4) << 4;

    for (int c = 0; c < 9; c++) {
        asm volatile("cp.async.wait_group 0;" ::: "memory");
        __syncthreads();   // chunk c visible; all warps done with the slot being refilled
        if (c + 1 < 9) {
            u32 sz; const unsigned char* s = chunk_src(c + 1, sz);
            u32 dst = sb + WOFF + (u32)((c + 1) & 1) * WSLOT;
            for (u32 r = tid * 16; r < sz; r += 4096) cp16(dst + r, s + r);
            asm volatile("cp.async.commit_group;");
        }

        if (c == 0 || c == 1 || c == 5) {
#pragma unroll
            for (int mt = 0; mt < 2; mt++)
#pragma unroll
                for (int nt = 0; nt < 8; nt++)
#pragma unroll
                    for (int q = 0; q < 4; q++) acc[mt][nt][q] = 0.f;
        }

        // ---- consume chunk c (64 k = 4 mma k-steps), pure fp16 ----
        const u32 wb = sb + WOFF + (u32)(c & 1) * WSLOT;
        const int lc = (c == 0) ? 0 : ((c < 5) ? c - 1 : c - 5);
        if (c < 5) {                                     // L0/L1: N=256
            const u32 b0a = wb + (u32)ng * 9216u + bladdr;
#pragma unroll
            for (int ks = 0; ks < 4; ks++) {
                u32 af[2][4];
                {
                    int akb = lc * 128 + ks * 32 + aksel;
#pragma unroll
                    for (int mt = 0; mt < 2; mt++)
                        ldsm4(af[mt], sb + aoff(arow0 + mt * 16, akb));
                }
                const u32 bks = b0a + (u32)ks * 32u;
#pragma unroll
                for (int np = 0; np < 4; np++) {
                    u32 b[4];
                    ldsm4(b, bks + (u32)np * 2304u);
#pragma unroll
                    for (int mt = 0; mt < 2; mt++) {
                        mma16816(acc[mt][2 * np],     af[mt], b);
                        mma16816(acc[mt][2 * np + 1], af[mt], b + 2);
                    }
                }
            }
        } else {                                         // L2: N=64
            const u32 b0a = wb + (u32)ng * 2304u + bladdr;
#pragma unroll
            for (int ks = 0; ks < 4; ks++) {
                u32 af[2][4];
                {
                    int akb = lc * 128 + ks * 32 + aksel;
#pragma unroll
                    for (int mt = 0; mt < 2; mt++)
                        ldsm4(af[mt], sb + aoff(arow0 + mt * 16, akb));
                }
                u32 b[4];
                ldsm4(b, b0a + (u32)ks * 32u);
#pragma unroll
                for (int mt = 0; mt < 2; mt++) {
                    mma16816(acc[mt][0], af[mt], b);
                    mma16816(acc[mt][1], af[mt], b + 2);
                }
            }
        }

        // ---- layer epilogues: softplus/JVP via lane-pair split (1 actf per lane) ----
        if (c == 0 || c == 4) {
            __syncthreads();   // all warps done ldsm-reading A plane before overwrite
            const float* bs = bias + ((c == 0) ? 0 : 256);
#pragma unroll
            for (int mt = 0; mt < 2; mt++)
#pragma unroll
                for (int nt = 0; nt < 8; nt++) {
                    int n = ng * 64 + nt * 8 + c2;
                    float b0v = ev ? bs[n] : 0.f, b1v = ev ? bs[n + 1] : 0.f;
#pragma unroll
                    for (int h = 0; h < 2; h++) {
                        int row = mg * 32 + mt * 16 + g + h * 8;
                        float z0 = acc[mt][nt][2 * h]     + b0v;
                        float z1 = acc[mt][nt][2 * h + 1] + b1v;
                        // pair L<->L^4 (primal/tangent partners, same n):
                        // even lane computes actf(own z0); odd lane computes actf(partner z1)
                        float zx = __shfl_xor_sync(0xffffffffu, z1, 4);
                        float zin = ev ? z0 : zx;
                        float sA, hA;
                        actf(zin, sA, hA);
                        float sB = __shfl_xor_sync(0xffffffffu, sA, 4);
                        float hB = __shfl_xor_sync(0xffffffffu, hA, 4);
                        // even: h0=hA, h1=hB ; odd: s0=sB, s1=sA
                        float v0 = ev ? hA : sB * z0;
                        float v1 = ev ? hB : sA * z1;
                        __half2 hp;
                        hp.x = __float2half_rn(v0); hp.y = __float2half_rn(v1);
                        *(__half2*)(sm + aoff(row, 2 * n)) = hp;
                    }
                }
            // next chunk's MMA reads are ordered by the next iteration's top __syncthreads
        }
    }

    // ---- final epilogue: dx (even rows) + divergence partials (odd rows) ----
    {
        const float* bs = bias + 512;
        float* dp = (float*)(sm + DIVOFF);
#pragma unroll
        for (int mt = 0; mt < 2; mt++)
#pragma unroll
            for (int h = 0; h < 2; h++) {
                int row = mg * 32 + mt * 16 + g + h * 8;
                int b = row >> 1;
                if (ev) {
#pragma unroll
                    for (int nt = 0; nt < 2; nt++) {
                        int n = ng * 16 + nt * 8 + c2;
                        out[(r0 + b) * 65 + n]     = acc[mt][nt][2 * h]     + bs[n];
                        out[(r0 + b) * 65 + n + 1] = acc[mt][nt][2 * h + 1] + bs[n + 1];
                    }
                } else {
                    float part = 0.f;
#pragma unroll
                    for (int nt = 0; nt < 2; nt++) {
                        int n = ng * 16 + nt * 8 + c2;
                        float2 ee = *(const float2*)&e[(r0 + b) * 64 + n];
                        part += acc[mt][nt][2 * h] * ee.x + acc[mt][nt][2 * h + 1] * ee.y;
                    }
                    dp[b * 16 + ng * 4 + (lane & 3)] = part;
                }
            }
    }
    __syncthreads();
    if (tid < 32) {
        const float* q = (const float*)(sm + DIVOFF) + tid * 16;
        float s = 0.f;
#pragma unroll
        for (int i = 0; i < 16; i++) s += q[i];
        out[(r0 + tid) * 65 + 64] = -s;
    }
}

// ---------------- launch ----------------
extern "C" void kernel_launch(void* const* d_in, const int* in_sizes, int n_in,
                              void* d_out, int out_size)
{
    const float* t  = (const float*)d_in[0];
    const float* y  = (const float*)d_in[1];
    const float* e  = (const float*)d_in[2];
    const float* W0 = (const float*)d_in[3];
    const float* b0 = (const float*)d_in[4];
    const float* W1 = (const float*)d_in[5];
    const float* b1 = (const float*)d_in[6];
    const float* W2 = (const float*)d_in[7];
    const float* b2 = (const float*)d_in[8];
    float* out = (float*)d_out;
    int B = in_sizes[1] / 65;

    cudaStreamCaptureStatus cs = cudaStreamCaptureStatusNone;
    cudaStreamIsCapturing((cudaStream_t)0, &cs);
    if (cs == cudaStreamCaptureStatusNone) {
        cudaFuncSetAttribute(odefunc_kernel,
                             cudaFuncAttributeMaxDynamicSharedMemorySize, SMEMSZ);
    }

    prep_kernel<<<256, 256>>>(t, W0, b0, W1, b1, W2, b2);
    odefunc_kernel<<<B / 32, 256, SMEMSZ>>>(y, e, out);
}